// round 6
// baseline (speedup 1.0000x reference)
#include <cuda_runtime.h>
#include <math.h>

#define NN   4096
#define DD   512
#define F1C  64
#define HC   4
#define HF   256   // HC*F1C
#define F2C  32
#define F3C  16
#define MAXD 128

// packed fp32x2 FMA (Blackwell)
#define FMA_F32X2(d, a, b, c) \
    asm("fma.rn.f32x2 %0, %1, %2, %3;" : "=l"(d) : "l"(a), "l"(b), "l"(c))
#define PACK2(out, lo, hi) \
    asm("mov.b64 %0, {%1, %2};" : "=l"(out) : "r"(lo), "r"(hi))
#define UNPACK2(lo, hi, in) \
    asm("mov.b64 {%0, %1}, %2;" : "=r"(lo), "=r"(hi) : "l"(in))

// float4 acc += w * v using two f32x2 FMAs (acc held as ulonglong2)
__device__ __forceinline__ void fma4w(ulonglong2& acc, float w, float4 v) {
    unsigned long long wp;
    PACK2(wp, __float_as_uint(w), __float_as_uint(w));
    ulonglong2 vv = *reinterpret_cast<ulonglong2*>(&v);
    FMA_F32X2(acc.x, wp, vv.x, acc.x);
    FMA_F32X2(acc.y, wp, vv.y, acc.y);
}
__device__ __forceinline__ float4 unpack4(ulonglong2 a) {
    unsigned u0, u1, u2, u3;
    UNPACK2(u0, u1, a.x);
    UNPACK2(u2, u3, a.y);
    return make_float4(__uint_as_float(u0), __uint_as_float(u1),
                       __uint_as_float(u2), __uint_as_float(u3));
}

// ---------------- scratch ---------------------------------------------------
__device__ int    g_deg[NN];
__device__ int    g_cols[NN * MAXD];
__device__ float  g_WhAll[NN * HF];      // [i][h*64+f]
__device__ float  g_s1v[NN * HC];        // [row][head]
__device__ float  g_s2v[NN * HC];
__device__ float4 g_wts1[NN * MAXD];     // normalized attn weights, 4 heads
__device__ float  g_cat[NN * HF];
__device__ float  g_Wh2[NN * F1C];
__device__ float  g_s1b[NN];
__device__ float  g_s2b[NN];
__device__ float  g_wts2[NN * MAXD];     // normalized attn weights (att GAT)
__device__ float  g_t1[NN * F2C];
__device__ float  g_t2[NN * F3C];
__device__ float  g_t3[NN * F3C];
__device__ float  g_z[NN * F3C];

// ============ fused: blocks [0,256) GEMM1 tiles, [256,768) build ELL ========
__global__ void k_build_gemm1(const float* __restrict__ adj,
                              const float* __restrict__ x,
                              const float* __restrict__ W_heads,
                              const float* __restrict__ a_heads) {
    __shared__ __align__(16) float sA[16][64];
    __shared__ __align__(16) float sB[16][64];
    int bx = blockIdx.x;
    if (bx >= 256) {
        int wb = bx - 256;
        int row = wb * 8 + (threadIdx.x >> 5);
        int lane = threadIdx.x & 31;
        const float4* arow = (const float4*)(adj + (size_t)row * NN);
        int cnt = 0;
        for (int j0 = 0; j0 < NN; j0 += 128) {
            float4 v = arow[(j0 >> 2) + lane];
            int base = j0 + lane * 4;
#pragma unroll
            for (int c = 0; c < 4; c++) {
                float val = (c == 0) ? v.x : (c == 1) ? v.y : (c == 2) ? v.z : v.w;
                unsigned m = __ballot_sync(0xffffffffu, val > 0.f);
                if (val > 0.f) {
                    int pos = cnt + __popc(m & ((1u << lane) - 1u));
                    if (pos < MAXD) g_cols[row * MAXD + pos] = base + c;
                }
                cnt += __popc(m);
            }
        }
        if (lane == 0) g_deg[row] = cnt < MAXD ? cnt : MAXD;
        return;
    }
    int head = bx >> 6;
    int bm = (bx & 63) << 6;
    int tid = threadIdx.x;
    int ty = tid >> 4, tx = tid & 15;
    const float* B = W_heads + (size_t)head * DD * F1C;
    unsigned long long acc2[4][2] = {};
    for (int k0 = 0; k0 < DD; k0 += 16) {
        int ar = tid >> 2, kq = (tid & 3) << 2;
        float4 va = *(const float4*)(x + (size_t)(bm + ar) * DD + k0 + kq);
        sA[kq + 0][ar] = va.x; sA[kq + 1][ar] = va.y;
        sA[kq + 2][ar] = va.z; sA[kq + 3][ar] = va.w;
        int br = tid >> 4, nq = (tid & 15) << 2;
        *(float4*)&sB[br][nq] = *(const float4*)(B + (size_t)(k0 + br) * F1C + nq);
        __syncthreads();
#pragma unroll
        for (int kk = 0; kk < 16; kk++) {
            float4 av = *(const float4*)&sA[kk][ty << 2];
            ulonglong2 bb = *(const ulonglong2*)&sB[kk][tx << 2];
            unsigned long long ap;
            PACK2(ap, __float_as_uint(av.x), __float_as_uint(av.x));
            FMA_F32X2(acc2[0][0], ap, bb.x, acc2[0][0]);
            FMA_F32X2(acc2[0][1], ap, bb.y, acc2[0][1]);
            PACK2(ap, __float_as_uint(av.y), __float_as_uint(av.y));
            FMA_F32X2(acc2[1][0], ap, bb.x, acc2[1][0]);
            FMA_F32X2(acc2[1][1], ap, bb.y, acc2[1][1]);
            PACK2(ap, __float_as_uint(av.z), __float_as_uint(av.z));
            FMA_F32X2(acc2[2][0], ap, bb.x, acc2[2][0]);
            FMA_F32X2(acc2[2][1], ap, bb.y, acc2[2][1]);
            PACK2(ap, __float_as_uint(av.w), __float_as_uint(av.w));
            FMA_F32X2(acc2[3][0], ap, bb.x, acc2[3][0]);
            FMA_F32X2(acc2[3][1], ap, bb.y, acc2[3][1]);
        }
        __syncthreads();
    }
    float acc[4][4];
#pragma unroll
    for (int i = 0; i < 4; i++) {
        float4 t = unpack4(*(ulonglong2*)acc2[i]);
        acc[i][0] = t.x; acc[i][1] = t.y; acc[i][2] = t.z; acc[i][3] = t.w;
    }
#pragma unroll
    for (int i = 0; i < 4; i++) {
        float4 v = make_float4(acc[i][0], acc[i][1], acc[i][2], acc[i][3]);
        *(float4*)(g_WhAll + (size_t)(bm + ty * 4 + i) * HF + head * F1C + (tx << 2)) = v;
    }
    const float* ag = a_heads + head * 2 * F1C;
    float a1v[4], a2v[4];
#pragma unroll
    for (int c = 0; c < 4; c++) { a1v[c] = ag[(tx << 2) + c]; a2v[c] = ag[F1C + (tx << 2) + c]; }
#pragma unroll
    for (int i = 0; i < 4; i++) {
        float p1 = acc[i][0] * a1v[0] + acc[i][1] * a1v[1] + acc[i][2] * a1v[2] + acc[i][3] * a1v[3];
        float p2 = acc[i][0] * a2v[0] + acc[i][1] * a2v[1] + acc[i][2] * a2v[2] + acc[i][3] * a2v[3];
#pragma unroll
        for (int o = 8; o; o >>= 1) {
            p1 += __shfl_xor_sync(0xffffffffu, p1, o);
            p2 += __shfl_xor_sync(0xffffffffu, p2, o);
        }
        if (tx == 0) {
            int row = bm + ty * 4 + i;
            g_s1v[row * HC + head] = p1;    // [row][head] for float4 gather
            g_s2v[row * HC + head] = p2;
        }
    }
}

// ---------------- soft1: warp per row, all 4 heads at once ------------------
__global__ void k_soft1() {
    int wid = threadIdx.x >> 5, lane = threadIdx.x & 31;
    int row = blockIdx.x * 8 + wid;
    int deg = g_deg[row];
    float4 s1 = *(const float4*)(g_s1v + row * HC);
    float4 ev[4];
    float4 m = make_float4(-1e30f, -1e30f, -1e30f, -1e30f);
#pragma unroll
    for (int jj = 0; jj < 4; jj++) {
        int j = lane + jj * 32;
        ev[jj] = make_float4(-1e30f, -1e30f, -1e30f, -1e30f);
        if (j < deg) {
            int col = g_cols[row * MAXD + j];
            float4 s2 = *(const float4*)(g_s2v + col * HC);
            float4 e;
            e.x = s1.x + s2.x; e.x = e.x >= 0.f ? e.x : 0.2f * e.x;
            e.y = s1.y + s2.y; e.y = e.y >= 0.f ? e.y : 0.2f * e.y;
            e.z = s1.z + s2.z; e.z = e.z >= 0.f ? e.z : 0.2f * e.z;
            e.w = s1.w + s2.w; e.w = e.w >= 0.f ? e.w : 0.2f * e.w;
            ev[jj] = e;
            m.x = fmaxf(m.x, e.x); m.y = fmaxf(m.y, e.y);
            m.z = fmaxf(m.z, e.z); m.w = fmaxf(m.w, e.w);
        }
    }
#pragma unroll
    for (int o = 16; o; o >>= 1) {
        m.x = fmaxf(m.x, __shfl_xor_sync(0xffffffffu, m.x, o));
        m.y = fmaxf(m.y, __shfl_xor_sync(0xffffffffu, m.y, o));
        m.z = fmaxf(m.z, __shfl_xor_sync(0xffffffffu, m.z, o));
        m.w = fmaxf(m.w, __shfl_xor_sync(0xffffffffu, m.w, o));
    }
    float4 s = make_float4(0.f, 0.f, 0.f, 0.f);
#pragma unroll
    for (int jj = 0; jj < 4; jj++) {
        int j = lane + jj * 32;
        if (j < deg) {
            float4 w;
            w.x = expf(ev[jj].x - m.x); w.y = expf(ev[jj].y - m.y);
            w.z = expf(ev[jj].z - m.z); w.w = expf(ev[jj].w - m.w);
            ev[jj] = w;
            s.x += w.x; s.y += w.y; s.z += w.z; s.w += w.w;
        }
    }
#pragma unroll
    for (int o = 16; o; o >>= 1) {
        s.x += __shfl_xor_sync(0xffffffffu, s.x, o);
        s.y += __shfl_xor_sync(0xffffffffu, s.y, o);
        s.z += __shfl_xor_sync(0xffffffffu, s.z, o);
        s.w += __shfl_xor_sync(0xffffffffu, s.w, o);
    }
    float4 inv = make_float4(1.f / s.x, 1.f / s.y, 1.f / s.z, 1.f / s.w);
#pragma unroll
    for (int jj = 0; jj < 4; jj++) {
        int j = lane + jj * 32;
        if (j < deg) {
            float4 w = ev[jj];
            g_wts1[row * MAXD + j] =
                make_float4(w.x * inv.x, w.y * inv.y, w.z * inv.z, w.w * inv.w);
        }
    }
}

// ---------------- agg1: 4 rows/block, float4 gather + ELU -------------------
__global__ void k_agg1() {
    __shared__ int   sdeg[4];
    __shared__ int   scols[4][MAXD];
    __shared__ __align__(16) float4 swts[4][MAXD];
    int tid = threadIdx.x;
    if (tid < 4) sdeg[tid] = g_deg[blockIdx.x * 4 + tid];
    __syncthreads();
    int r = tid >> 6, t = tid & 63;
    int row = blockIdx.x * 4 + r;
    int deg = sdeg[r];
    for (int j = t; j < deg; j += 64) {
        scols[r][j] = g_cols[row * MAXD + j];
        swts[r][j] = g_wts1[row * MAXD + j];
    }
    __syncthreads();
    int g = t >> 4, f4 = (t & 15) << 2;
    const float* wf = (const float*)swts[r];
    const float* base = g_WhAll + g * F1C + f4;
    ulonglong2 a0 = {0, 0}, a1 = {0, 0}, a2 = {0, 0}, a3 = {0, 0};
    int j = 0;
    for (; j + 4 <= deg; j += 4) {
        fma4w(a0, wf[(j + 0) * 4 + g], *(const float4*)(base + (size_t)scols[r][j + 0] * HF));
        fma4w(a1, wf[(j + 1) * 4 + g], *(const float4*)(base + (size_t)scols[r][j + 1] * HF));
        fma4w(a2, wf[(j + 2) * 4 + g], *(const float4*)(base + (size_t)scols[r][j + 2] * HF));
        fma4w(a3, wf[(j + 3) * 4 + g], *(const float4*)(base + (size_t)scols[r][j + 3] * HF));
    }
    for (; j < deg; j++)
        fma4w(a0, wf[j * 4 + g], *(const float4*)(base + (size_t)scols[r][j] * HF));
    float4 v0 = unpack4(a0), v1 = unpack4(a1), v2 = unpack4(a2), v3 = unpack4(a3);
    float4 o;
    o.x = (v0.x + v1.x) + (v2.x + v3.x);
    o.y = (v0.y + v1.y) + (v2.y + v3.y);
    o.z = (v0.z + v1.z) + (v2.z + v3.z);
    o.w = (v0.w + v1.w) + (v2.w + v3.w);
    o.x = o.x > 0.f ? o.x : expm1f(o.x);
    o.y = o.y > 0.f ? o.y : expm1f(o.y);
    o.z = o.z > 0.f ? o.z : expm1f(o.z);
    o.w = o.w > 0.f ? o.w : expm1f(o.w);
    *(float4*)(g_cat + (size_t)row * HF + g * F1C + f4) = o;
}

// ---------------- GEMM2: Wh2 = cat @ W_att (BM=16, 256 CTAs) + scores ------
__global__ void k_gemm2(const float* __restrict__ W_att,
                        const float* __restrict__ a_att) {
    __shared__ __align__(16) float sA[32][17];
    __shared__ __align__(16) float sB[32][64];
    int bm = blockIdx.x << 4;
    int tid = threadIdx.x;
    int row = tid >> 4, cq = (tid & 15) << 2;
    unsigned long long acc2[2] = {};
    for (int k0 = 0; k0 < HF; k0 += 32) {
        if (tid < 128) {
            int r = tid >> 3, kq = (tid & 7) << 2;
            float4 va = *(const float4*)(g_cat + (size_t)(bm + r) * HF + k0 + kq);
            sA[kq + 0][r] = va.x; sA[kq + 1][r] = va.y;
            sA[kq + 2][r] = va.z; sA[kq + 3][r] = va.w;
        }
#pragma unroll
        for (int t = 0; t < 2; t++) {
            int idx = tid + t * 256;
            int kr = idx >> 4, bq = (idx & 15) << 2;
            *(float4*)&sB[kr][bq] = *(const float4*)(W_att + (size_t)(k0 + kr) * F1C + bq);
        }
        __syncthreads();
#pragma unroll
        for (int kk = 0; kk < 32; kk++) {
            float a = sA[kk][row];
            ulonglong2 bb = *(const ulonglong2*)&sB[kk][cq];
            unsigned long long ap;
            PACK2(ap, __float_as_uint(a), __float_as_uint(a));
            FMA_F32X2(acc2[0], ap, bb.x, acc2[0]);
            FMA_F32X2(acc2[1], ap, bb.y, acc2[1]);
        }
        __syncthreads();
    }
    float4 v = unpack4(*(ulonglong2*)acc2);
    *(float4*)(g_Wh2 + (size_t)(bm + row) * F1C + cq) = v;
    float p1 = v.x * a_att[cq] + v.y * a_att[cq + 1] + v.z * a_att[cq + 2] + v.w * a_att[cq + 3];
    float p2 = v.x * a_att[F1C + cq] + v.y * a_att[F1C + cq + 1]
             + v.z * a_att[F1C + cq + 2] + v.w * a_att[F1C + cq + 3];
#pragma unroll
    for (int o = 8; o; o >>= 1) {
        p1 += __shfl_xor_sync(0xffffffffu, p1, o);
        p2 += __shfl_xor_sync(0xffffffffu, p2, o);
    }
    if ((tid & 15) == 0) {
        g_s1b[bm + row] = p1;
        g_s2b[bm + row] = p2;
    }
}

// ---------------- soft2: warp per row (scalar head) -------------------------
__global__ void k_soft2() {
    int wid = threadIdx.x >> 5, lane = threadIdx.x & 31;
    int row = blockIdx.x * 8 + wid;
    int deg = g_deg[row];
    float s1 = g_s1b[row];
    float ev[4];
    float m = -1e30f;
#pragma unroll
    for (int jj = 0; jj < 4; jj++) {
        int j = lane + jj * 32;
        ev[jj] = -1e30f;
        if (j < deg) {
            float e = s1 + g_s2b[g_cols[row * MAXD + j]];
            e = e >= 0.f ? e : 0.2f * e;
            ev[jj] = e;
            m = fmaxf(m, e);
        }
    }
#pragma unroll
    for (int o = 16; o; o >>= 1) m = fmaxf(m, __shfl_xor_sync(0xffffffffu, m, o));
    float s = 0.f;
#pragma unroll
    for (int jj = 0; jj < 4; jj++) {
        int j = lane + jj * 32;
        if (j < deg) {
            float w = expf(ev[jj] - m);
            ev[jj] = w;
            s += w;
        }
    }
#pragma unroll
    for (int o = 16; o; o >>= 1) s += __shfl_xor_sync(0xffffffffu, s, o);
    float inv = 1.f / s;
#pragma unroll
    for (int jj = 0; jj < 4; jj++) {
        int j = lane + jj * 32;
        if (j < deg) g_wts2[row * MAXD + j] = ev[jj] * inv;
    }
}

// ---------------- agg2 + fc1: 16 rows/block, float4 gather ------------------
__global__ void k_agg2_fc1(const float* __restrict__ W1) {
    __shared__ int   sdeg[16];
    __shared__ int   scols[16][MAXD];
    __shared__ float swts[16][MAXD];
    __shared__ float sgc[16][F1C];
    __shared__ float sW1[F1C * F2C];
    int tid = threadIdx.x;
    for (int k = tid; k < F1C * F2C; k += 256) sW1[k] = W1[k];
    if (tid < 16) sdeg[tid] = g_deg[blockIdx.x * 16 + tid];
    __syncthreads();
    int r = tid >> 4, t = tid & 15;
    int row = blockIdx.x * 16 + r;
    int deg = sdeg[r];
    for (int j = t; j < deg; j += 16) {
        scols[r][j] = g_cols[row * MAXD + j];
        swts[r][j] = g_wts2[row * MAXD + j];
    }
    __syncthreads();
    int f4 = t << 2;
    const float* base = g_Wh2 + f4;
    ulonglong2 a0 = {0, 0}, a1 = {0, 0}, a2 = {0, 0}, a3 = {0, 0};
    int j = 0;
    for (; j + 4 <= deg; j += 4) {
        fma4w(a0, swts[r][j + 0], *(const float4*)(base + (size_t)scols[r][j + 0] * F1C));
        fma4w(a1, swts[r][j + 1], *(const float4*)(base + (size_t)scols[r][j + 1] * F1C));
        fma4w(a2, swts[r][j + 2], *(const float4*)(base + (size_t)scols[r][j + 2] * F1C));
        fma4w(a3, swts[r][j + 3], *(const float4*)(base + (size_t)scols[r][j + 3] * F1C));
    }
    for (; j < deg; j++)
        fma4w(a0, swts[r][j], *(const float4*)(base + (size_t)scols[r][j] * F1C));
    float4 v0 = unpack4(a0), v1 = unpack4(a1), v2 = unpack4(a2), v3 = unpack4(a3);
    float4 o;
    o.x = (v0.x + v1.x) + (v2.x + v3.x);
    o.y = (v0.y + v1.y) + (v2.y + v3.y);
    o.z = (v0.z + v1.z) + (v2.z + v3.z);
    o.w = (v0.w + v1.w) + (v2.w + v3.w);
    sgc[r][f4 + 0] = o.x > 0.f ? o.x : expm1f(o.x);
    sgc[r][f4 + 1] = o.y > 0.f ? o.y : expm1f(o.y);
    sgc[r][f4 + 2] = o.z > 0.f ? o.z : expm1f(o.z);
    sgc[r][f4 + 3] = o.w > 0.f ? o.w : expm1f(o.w);
    __syncthreads();
    // fc1: 16 rows x 32 outputs, thread -> (r, c) and (r, c+16)
    int c = t;
    float ta = 0.f, tb = 0.f;
#pragma unroll 16
    for (int k = 0; k < F1C; k++) {
        float h = sgc[r][k];
        ta += h * sW1[k * F2C + c];
        tb += h * sW1[k * F2C + c + 16];
    }
    g_t1[row * F2C + c] = ta;
    g_t1[row * F2C + c + 16] = tb;
}

// ---------------- h1 = relu(adj@t1) + t2=h1@W2, t3=h1@W3 (32 rows/block) ---
__global__ void k_spmm_fc23(const float* __restrict__ W2,
                            const float* __restrict__ W3) {
    __shared__ int   sdeg[32];
    __shared__ int   scols[32][MAXD];
    __shared__ float sh[32][F2C];
    __shared__ float sw23[2 * F2C * F3C];
    int tid = threadIdx.x;
    for (int k = tid; k < F2C * F3C; k += 256) { sw23[k] = W2[k]; sw23[F2C * F3C + k] = W3[k]; }
    if (tid < 32) sdeg[tid] = g_deg[blockIdx.x * 32 + tid];
    __syncthreads();
    int r = tid >> 3, t = tid & 7;
    int row = blockIdx.x * 32 + r;
    int deg = sdeg[r];
    for (int j = t; j < deg; j += 8) scols[r][j] = g_cols[row * MAXD + j];
    __syncwarp();
    __syncthreads();
    int f4 = t << 2;
    const float* base = g_t1 + f4;
    ulonglong2 a0 = {0, 0}, a1 = {0, 0}, a2 = {0, 0}, a3 = {0, 0};
    unsigned long long one;
    PACK2(one, __float_as_uint(1.f), __float_as_uint(1.f));
    int j = 0;
    for (; j + 4 <= deg; j += 4) {
        ulonglong2 v0 = *(const ulonglong2*)(base + (size_t)scols[r][j + 0] * F2C);
        ulonglong2 v1 = *(const ulonglong2*)(base + (size_t)scols[r][j + 1] * F2C);
        ulonglong2 v2 = *(const ulonglong2*)(base + (size_t)scols[r][j + 2] * F2C);
        ulonglong2 v3 = *(const ulonglong2*)(base + (size_t)scols[r][j + 3] * F2C);
        FMA_F32X2(a0.x, one, v0.x, a0.x); FMA_F32X2(a0.y, one, v0.y, a0.y);
        FMA_F32X2(a1.x, one, v1.x, a1.x); FMA_F32X2(a1.y, one, v1.y, a1.y);
        FMA_F32X2(a2.x, one, v2.x, a2.x); FMA_F32X2(a2.y, one, v2.y, a2.y);
        FMA_F32X2(a3.x, one, v3.x, a3.x); FMA_F32X2(a3.y, one, v3.y, a3.y);
    }
    for (; j < deg; j++) {
        ulonglong2 v0 = *(const ulonglong2*)(base + (size_t)scols[r][j] * F2C);
        FMA_F32X2(a0.x, one, v0.x, a0.x); FMA_F32X2(a0.y, one, v0.y, a0.y);
    }
    float4 v0 = unpack4(a0), v1 = unpack4(a1), v2 = unpack4(a2), v3 = unpack4(a3);
    sh[r][f4 + 0] = fmaxf((v0.x + v1.x) + (v2.x + v3.x), 0.f);
    sh[r][f4 + 1] = fmaxf((v0.y + v1.y) + (v2.y + v3.y), 0.f);
    sh[r][f4 + 2] = fmaxf((v0.z + v1.z) + (v2.z + v3.z), 0.f);
    sh[r][f4 + 3] = fmaxf((v0.w + v1.w) + (v2.w + v3.w), 0.f);
    __syncthreads();
    // 32 rows x (16 t2 + 16 t3) outputs = 1024; thread -> 4 outputs (float4)
    int o = t << 2;                    // 0,4,8,...,28
    const float* w = (o < 16) ? sw23 : sw23 + F2C * F3C;
    int f = o & 15;
    float q0 = 0.f, q1 = 0.f, q2 = 0.f, q3 = 0.f;
#pragma unroll 8
    for (int k = 0; k < F2C; k++) {
        float h = sh[r][k];
        q0 += h * w[k * F3C + f + 0];
        q1 += h * w[k * F3C + f + 1];
        q2 += h * w[k * F3C + f + 2];
        q3 += h * w[k * F3C + f + 3];
    }
    float* dst = (o < 16) ? g_t2 : g_t3;
    *(float4*)(dst + row * F3C + f) = make_float4(q0, q1, q2, q3);
}

// ---------------- mu/logvar spmm + reparameterize (32 rows/block) ----------
__global__ void k_spmm_reparam(const float* __restrict__ eps,
                               float* __restrict__ out_mu,
                               float* __restrict__ out_lv) {
    __shared__ int   sdeg[32];
    __shared__ int   scols[32][MAXD];
    __shared__ float smu[32][F3C];
    __shared__ float slv[32][F3C];
    int tid = threadIdx.x;
    if (tid < 32) sdeg[tid] = g_deg[blockIdx.x * 32 + tid];
    __syncthreads();
    int r = tid >> 3, t = tid & 7;
    int row = blockIdx.x * 32 + r;
    int deg = sdeg[r];
    for (int j = t; j < deg; j += 8) scols[r][j] = g_cols[row * MAXD + j];
    __syncthreads();
    const float* src = (t < 4) ? g_t2 : g_t3;
    int f4 = (t & 3) << 2;
    const float* base = src + f4;
    ulonglong2 a0 = {0, 0}, a1 = {0, 0};
    unsigned long long one;
    PACK2(one, __float_as_uint(1.f), __float_as_uint(1.f));
    int j = 0;
    for (; j + 2 <= deg; j += 2) {
        ulonglong2 v0 = *(const ulonglong2*)(base + (size_t)scols[r][j + 0] * F3C);
        ulonglong2 v1 = *(const ulonglong2*)(base + (size_t)scols[r][j + 1] * F3C);
        FMA_F32X2(a0.x, one, v0.x, a0.x); FMA_F32X2(a0.y, one, v0.y, a0.y);
        FMA_F32X2(a1.x, one, v1.x, a1.x); FMA_F32X2(a1.y, one, v1.y, a1.y);
    }
    if (j < deg) {
        ulonglong2 v0 = *(const ulonglong2*)(base + (size_t)scols[r][j] * F3C);
        FMA_F32X2(a0.x, one, v0.x, a0.x); FMA_F32X2(a0.y, one, v0.y, a0.y);
    }
    float4 v0 = unpack4(a0), v1 = unpack4(a1);
    float4 res = make_float4(v0.x + v1.x, v0.y + v1.y, v0.z + v1.z, v0.w + v1.w);
    float* dst = (t < 4) ? &smu[r][f4] : &slv[r][f4];
    *(float4*)dst = res;
    __syncthreads();
    // 32 rows x 16 = 512 z values; thread -> 2
    int idx = tid * 2;
    int zr = idx >> 4, zf = idx & 15;
    int zrow = blockIdx.x * 32 + zr;
#pragma unroll
    for (int u = 0; u < 2; u++) {
        float mu = smu[zr][zf + u], lv = slv[zr][zf + u];
        int o = zrow * F3C + zf + u;
        out_mu[o] = mu;
        out_lv[o] = lv;
        g_z[o] = eps[o] * expf(lv) + mu;
    }
}

// ---------------- adj_rec = z @ z^T ----------------------------------------
__global__ void k_zzT(float* __restrict__ out) {
    __shared__ float sa[64][17];
    __shared__ float sb[64][17];
    int bi = blockIdx.y << 6, bj = blockIdx.x << 6;
    int tid = threadIdx.x;
    int r = tid >> 2, q = (tid & 3) << 2;
    float4 va = *(const float4*)(g_z + ((bi + r) << 4) + q);
    sa[r][q + 0] = va.x; sa[r][q + 1] = va.y; sa[r][q + 2] = va.z; sa[r][q + 3] = va.w;
    float4 vb = *(const float4*)(g_z + ((bj + r) << 4) + q);
    sb[r][q + 0] = vb.x; sb[r][q + 1] = vb.y; sb[r][q + 2] = vb.z; sb[r][q + 3] = vb.w;
    __syncthreads();
    int ty = tid >> 4, tx = tid & 15;
    float acc[4][4] = {};
#pragma unroll
    for (int k = 0; k < 16; k++) {
        float a0 = sa[ty * 4 + 0][k], a1 = sa[ty * 4 + 1][k];
        float a2 = sa[ty * 4 + 2][k], a3 = sa[ty * 4 + 3][k];
        float b0 = sb[tx * 4 + 0][k], b1 = sb[tx * 4 + 1][k];
        float b2 = sb[tx * 4 + 2][k], b3 = sb[tx * 4 + 3][k];
        acc[0][0] += a0 * b0; acc[0][1] += a0 * b1; acc[0][2] += a0 * b2; acc[0][3] += a0 * b3;
        acc[1][0] += a1 * b0; acc[1][1] += a1 * b1; acc[1][2] += a1 * b2; acc[1][3] += a1 * b3;
        acc[2][0] += a2 * b0; acc[2][1] += a2 * b1; acc[2][2] += a2 * b2; acc[2][3] += a2 * b3;
        acc[3][0] += a3 * b0; acc[3][1] += a3 * b1; acc[3][2] += a3 * b2; acc[3][3] += a3 * b3;
    }
#pragma unroll
    for (int i = 0; i < 4; i++) {
        float4 v = make_float4(acc[i][0], acc[i][1], acc[i][2], acc[i][3]);
        *(float4*)(out + (size_t)(bi + ty * 4 + i) * NN + bj + (tx << 2)) = v;
    }
}

// ---------------- launch ----------------------------------------------------
extern "C" void kernel_launch(void* const* d_in, const int* in_sizes, int n_in,
                              void* d_out, int out_size) {
    const float* x       = (const float*)d_in[0];
    const float* adj     = (const float*)d_in[1];
    const float* W_heads = (const float*)d_in[2];
    const float* a_heads = (const float*)d_in[3];
    const float* W_att   = (const float*)d_in[4];
    const float* a_att   = (const float*)d_in[5];
    const float* W1      = (const float*)d_in[6];
    const float* W2      = (const float*)d_in[7];
    const float* W3      = (const float*)d_in[8];
    const float* eps     = (const float*)d_in[9];
    float* out = (float*)d_out;
    float* out_mu = out + (size_t)NN * NN;
    float* out_lv = out_mu + (size_t)NN * F3C;

    k_build_gemm1<<<768, 256>>>(adj, x, W_heads, a_heads);
    k_soft1<<<NN / 8, 256>>>();
    k_agg1<<<NN / 4, 256>>>();
    k_gemm2<<<NN / 16, 256>>>(W_att, a_att);
    k_soft2<<<NN / 8, 256>>>();
    k_agg2_fc1<<<NN / 16, 256>>>(W1);
    k_spmm_fc23<<<NN / 32, 256>>>(W2, W3);
    k_spmm_reparam<<<NN / 32, 256>>>(eps, out_mu, out_lv);
    k_zzT<<<dim3(NN / 64, NN / 64), 256>>>(out);
}